// round 2
// baseline (speedup 1.0000x reference)
#include <cuda_runtime.h>
#include <cuda_bf16.h>
#include <math.h>

// Problem constants
#define LSEQ 48
#define BATCH 8192
#define EDIM 50
#define HDIM 512
#define VOCAB 128
#define NG   (4 * HDIM)      // 2048 packed gate columns (n = h*4 + g)
#define KH   512             // GEMM K (hidden only; emb part folded into Xg table)

// ---------------- scratch (static __device__ arrays; no allocation) ----------
__device__ float g_WpTd[(size_t)KH * 2 * NG];      // [k][2n]: duplicated pairs {w,w}  (8 MB)
__device__ float g_WoTd[(size_t)KH * 2 * VOCAB];   // [k][2v]: duplicated W_out       (0.5 MB)
__device__ float g_bsum[NG];                       // b_ih + b_hh, packed order
__device__ float g_Xg[(size_t)VOCAB * NG];         // emb @ W_ih^T, packed order (1 MB)
__device__ float g_HT[(size_t)(LSEQ + 1) * HDIM * BATCH];  // h_t transposed [t][h][b] (822 MB)
__device__ float g_CT[(size_t)HDIM * BATCH];       // cell state transposed [h][b] (16 MB)

// ---------------- helpers ----------------------------------------------------
__device__ __forceinline__ void fma2(unsigned long long &d, unsigned long long a, unsigned long long b) {
    asm("fma.rn.f32x2 %0, %1, %2, %0;" : "+l"(d) : "l"(a), "l"(b));
}
__device__ __forceinline__ void upk2(unsigned long long v, float &lo, float &hi) {
    asm("mov.b64 {%0, %1}, %2;" : "=f"(lo), "=f"(hi) : "l"(v));
}
__device__ __forceinline__ float sigm(float x) { return 1.0f / (1.0f + expf(-x)); }

#define CP16(dst, src) asm volatile("cp.async.cg.shared.global [%0], [%1], 16;" :: "r"(dst), "l"(src))
#define CP_COMMIT()    asm volatile("cp.async.commit_group;")
#define CP_WAIT0()     asm volatile("cp.async.wait_group 0;")

// ---------------- prep: pack + transpose + duplicate weights -------------------
__global__ void prep_kernel(const float* __restrict__ W_hh,
                            const float* __restrict__ W_out,
                            const float* __restrict__ b_ih,
                            const float* __restrict__ b_hh) {
    const size_t nWp = (size_t)KH * 2 * NG;      // 2M
    for (size_t i = (size_t)blockIdx.x * blockDim.x + threadIdx.x; i < nWp;
         i += (size_t)gridDim.x * blockDim.x) {
        int k = (int)(i / (2 * NG));
        int q = (int)(i % (2 * NG));
        int n = q >> 1;
        int h = n >> 2, g = n & 3;
        g_WpTd[i] = W_hh[(size_t)(g * HDIM + h) * HDIM + k];
    }
    const size_t nWo = (size_t)KH * 2 * VOCAB;   // 128K
    for (size_t i = (size_t)blockIdx.x * blockDim.x + threadIdx.x; i < nWo;
         i += (size_t)gridDim.x * blockDim.x) {
        int k = (int)(i / (2 * VOCAB));
        int q = (int)(i % (2 * VOCAB));
        int v = q >> 1;
        g_WoTd[i] = W_out[(size_t)v * HDIM + k];
    }
    int j = blockIdx.x * blockDim.x + threadIdx.x;
    if (j < NG) {
        int h = j >> 2, g = j & 3;
        g_bsum[j] = b_ih[g * HDIM + h] + b_hh[g * HDIM + h];
    }
}

// Xg[v][n] = sum_e emb[v][e] * W_ih[g*H+h][e],  n = h*4+g
__global__ void xg_tab_kernel(const float* __restrict__ emb,
                              const float* __restrict__ W_ih) {
    int i = blockIdx.x * blockDim.x + threadIdx.x;   // 128*2048 threads
    if (i >= VOCAB * NG) return;
    int v = i >> 11, n = i & (NG - 1);
    int h = n >> 2, g = n & 3;
    const float* er = emb + (size_t)v * EDIM;
    const float* wr = W_ih + (size_t)(g * HDIM + h) * EDIM;
    float s = 0.0f;
    #pragma unroll
    for (int e = 0; e < EDIM; ++e) s += er[e] * wr[e];
    g_Xg[i] = s;
}

// transpose h0,c0 [b][h] -> [h][b]
__global__ void transpose_in_kernel(const float* __restrict__ h0,
                                    const float* __restrict__ c0) {
    __shared__ float th[32][33], tc[32][33];
    int bb = blockIdx.x * 32, hh = blockIdx.y * 32;
    int x = threadIdx.x, y = threadIdx.y;  // 32 x 8
    for (int i = y; i < 32; i += 8) {
        th[i][x] = h0[(size_t)(bb + i) * HDIM + hh + x];
        tc[i][x] = c0[(size_t)(bb + i) * HDIM + hh + x];
    }
    __syncthreads();
    for (int i = y; i < 32; i += 8) {
        g_HT[(size_t)(hh + i) * BATCH + bb + x] = th[x][i];
        g_CT[(size_t)(hh + i) * BATCH + bb + x] = tc[x][i];
    }
}

// ---------------- fused gate GEMM + LSTM cell (one time step) -----------------
// gates[b][n] = sum_k HT[t][k][b] * Wp[n][k];  then LSTM cell fused in epilogue.
// Block tile 128(m=b) x 128(n), BK=16, 256 threads, 8x8 micro-tile,
// double-buffered cp.async, B pre-duplicated for f32x2.
__global__ __launch_bounds__(256, 2)
void lstm_step_kernel(int t, const int* __restrict__ input) {
    extern __shared__ float smem[];
    float* sA = smem;                  // [2][16][128]
    float* sB = smem + 2 * 16 * 128;   // [2][16][256]

    const int tid = threadIdx.x;
    const int bm0 = blockIdx.x * 128;
    const int n0  = blockIdx.y * 128;

    const float* Asrc = g_HT + (size_t)t * HDIM * BATCH;    // [k][b]
    const float* Bsrc = g_WpTd + (size_t)2 * n0;            // [k][2n] slice

    // loader mapping
    const int lk = tid >> 4;            // k-row 0..15
    const int la = (tid & 15) * 8;      // A: 8 floats (2 chunks)
    const int lb = (tid & 15) * 16;     // B: 16 floats (4 chunks)

    // compute mapping: warp 4x2 grid, lane 4x8
    const int w = tid >> 5, lane = tid & 31;
    const int mt = (w & 3) * 32 + (lane >> 3) * 8;   // 8 rows mt..mt+7
    const int nt = (w >> 2) * 64 + (lane & 7) * 8;   // 8 cols nt..nt+7

    unsigned long long acc[8][4];
    #pragma unroll
    for (int j = 0; j < 8; ++j)
        #pragma unroll
        for (int i = 0; i < 4; ++i) acc[j][i] = 0ULL;

    // ---- issue stage 0 ----
    {
        const float* ga = Asrc + (size_t)lk * BATCH + bm0 + la;
        unsigned da = (unsigned)__cvta_generic_to_shared(sA + lk * 128 + la);
        CP16(da, ga); CP16(da + 16, ga + 4);
        const float* gb = Bsrc + (size_t)lk * (2 * NG) + lb;
        unsigned db = (unsigned)__cvta_generic_to_shared(sB + lk * 256 + lb);
        CP16(db, gb); CP16(db + 16, gb + 4); CP16(db + 32, gb + 8); CP16(db + 48, gb + 12);
        CP_COMMIT();
    }

    const int KT = KH / 16;  // 32
    for (int kt = 0; kt < KT; ++kt) {
        CP_WAIT0();
        __syncthreads();
        // issue next stage
        if (kt + 1 < KT) {
            const int s = (kt + 1) & 1;
            const int k0 = (kt + 1) * 16;
            const float* ga = Asrc + (size_t)(k0 + lk) * BATCH + bm0 + la;
            unsigned da = (unsigned)__cvta_generic_to_shared(sA + (s * 16 + lk) * 128 + la);
            CP16(da, ga); CP16(da + 16, ga + 4);
            const float* gb = Bsrc + (size_t)(k0 + lk) * (2 * NG) + lb;
            unsigned db = (unsigned)__cvta_generic_to_shared(sB + (s * 16 + lk) * 256 + lb);
            CP16(db, gb); CP16(db + 16, gb + 4); CP16(db + 32, gb + 8); CP16(db + 48, gb + 12);
            CP_COMMIT();
        }
        // compute current stage
        const int s = kt & 1;
        const float* pa_base = sA + s * 16 * 128 + mt;
        const float* pb_base = sB + s * 16 * 256 + nt * 2;
        #pragma unroll
        for (int kk = 0; kk < 16; ++kk) {
            ulonglong2 a01 = *reinterpret_cast<const ulonglong2*>(pa_base + kk * 128);
            ulonglong2 a23 = *reinterpret_cast<const ulonglong2*>(pa_base + kk * 128 + 4);
            ulonglong2 b01 = *reinterpret_cast<const ulonglong2*>(pb_base + kk * 256);
            ulonglong2 b23 = *reinterpret_cast<const ulonglong2*>(pb_base + kk * 256 + 4);
            ulonglong2 b45 = *reinterpret_cast<const ulonglong2*>(pb_base + kk * 256 + 8);
            ulonglong2 b67 = *reinterpret_cast<const ulonglong2*>(pb_base + kk * 256 + 12);
            unsigned long long ap[4] = { a01.x, a01.y, a23.x, a23.y };
            unsigned long long bp[8] = { b01.x, b01.y, b23.x, b23.y, b45.x, b45.y, b67.x, b67.y };
            #pragma unroll
            for (int j = 0; j < 8; ++j)
                #pragma unroll
                for (int i = 0; i < 4; ++i)
                    fma2(acc[j][i], ap[i], bp[j]);
        }
    }

    // ---- epilogue: bias + Xg + LSTM cell ----
    float av[8][8];
    #pragma unroll
    for (int j = 0; j < 8; ++j)
        #pragma unroll
        for (int i = 0; i < 4; ++i) upk2(acc[j][i], av[j][2 * i], av[j][2 * i + 1]);

    const float4 bs0 = *reinterpret_cast<const float4*>(&g_bsum[n0 + nt]);
    const float4 bs1 = *reinterpret_cast<const float4*>(&g_bsum[n0 + nt + 4]);
    const int hA = (n0 + nt) >> 2;
    const int hB = hA + 1;
    const size_t cAo = (size_t)hA * BATCH, cBo = (size_t)hB * BATCH;
    float* Hout = g_HT + (size_t)(t + 1) * HDIM * BATCH;
    const int* idx_t = input + (size_t)t * BATCH;

    #pragma unroll
    for (int p = 0; p < 8; ++p) {
        const int b = bm0 + mt + p;
        const int v = idx_t[b];
        const float4 x0 = *reinterpret_cast<const float4*>(&g_Xg[(size_t)v * NG + n0 + nt]);
        const float4 x1 = *reinterpret_cast<const float4*>(&g_Xg[(size_t)v * NG + n0 + nt + 4]);
        {
            float gi = av[0][p] + bs0.x + x0.x;
            float gf = av[1][p] + bs0.y + x0.y;
            float gg = av[2][p] + bs0.z + x0.z;
            float go = av[3][p] + bs0.w + x0.w;
            float co = g_CT[cAo + b];
            float cn = sigm(gf) * co + sigm(gi) * tanhf(gg);
            g_CT[cAo + b] = cn;
            Hout[cAo + b] = sigm(go) * tanhf(cn);
        }
        {
            float gi = av[4][p] + bs1.x + x1.x;
            float gf = av[5][p] + bs1.y + x1.y;
            float gg = av[6][p] + bs1.z + x1.z;
            float go = av[7][p] + bs1.w + x1.w;
            float co = g_CT[cBo + b];
            float cn = sigm(gf) * co + sigm(gi) * tanhf(gg);
            g_CT[cBo + b] = cn;
            Hout[cBo + b] = sigm(go) * tanhf(cn);
        }
    }
}

// ---------------- batched output projection -----------------------------------
// scores[t*B+b][v] = sum_k HT[t+1][k][b] * W_out[v][k] + b_out[v]
__global__ __launch_bounds__(256, 2)
void out_gemm_kernel(const float* __restrict__ b_out, float* __restrict__ out) {
    extern __shared__ float smem[];
    float* sA = smem;
    float* sB = smem + 2 * 16 * 128;

    const int tid = threadIdx.x;
    const int t   = blockIdx.x >> 6;
    const int bm0 = (blockIdx.x & 63) * 128;

    const float* Asrc = g_HT + (size_t)(t + 1) * HDIM * BATCH;  // [k][b]
    const float* Bsrc = g_WoTd;                                  // [k][256]

    const int lk = tid >> 4;
    const int la = (tid & 15) * 8;
    const int lb = (tid & 15) * 16;

    const int w = tid >> 5, lane = tid & 31;
    const int mt = (w & 3) * 32 + (lane >> 3) * 8;
    const int nt = (w >> 2) * 64 + (lane & 7) * 8;

    unsigned long long acc[8][4];
    #pragma unroll
    for (int j = 0; j < 8; ++j)
        #pragma unroll
        for (int i = 0; i < 4; ++i) acc[j][i] = 0ULL;

    {
        const float* ga = Asrc + (size_t)lk * BATCH + bm0 + la;
        unsigned da = (unsigned)__cvta_generic_to_shared(sA + lk * 128 + la);
        CP16(da, ga); CP16(da + 16, ga + 4);
        const float* gb = Bsrc + (size_t)lk * 256 + lb;
        unsigned db = (unsigned)__cvta_generic_to_shared(sB + lk * 256 + lb);
        CP16(db, gb); CP16(db + 16, gb + 4); CP16(db + 32, gb + 8); CP16(db + 48, gb + 12);
        CP_COMMIT();
    }

    const int KT = KH / 16;
    for (int kt = 0; kt < KT; ++kt) {
        CP_WAIT0();
        __syncthreads();
        if (kt + 1 < KT) {
            const int s = (kt + 1) & 1;
            const int k0 = (kt + 1) * 16;
            const float* ga = Asrc + (size_t)(k0 + lk) * BATCH + bm0 + la;
            unsigned da = (unsigned)__cvta_generic_to_shared(sA + (s * 16 + lk) * 128 + la);
            CP16(da, ga); CP16(da + 16, ga + 4);
            const float* gb = Bsrc + (size_t)(k0 + lk) * 256 + lb;
            unsigned db = (unsigned)__cvta_generic_to_shared(sB + (s * 16 + lk) * 256 + lb);
            CP16(db, gb); CP16(db + 16, gb + 4); CP16(db + 32, gb + 8); CP16(db + 48, gb + 12);
            CP_COMMIT();
        }
        const int s = kt & 1;
        const float* pa_base = sA + s * 16 * 128 + mt;
        const float* pb_base = sB + s * 16 * 256 + nt * 2;
        #pragma unroll
        for (int kk = 0; kk < 16; ++kk) {
            ulonglong2 a01 = *reinterpret_cast<const ulonglong2*>(pa_base + kk * 128);
            ulonglong2 a23 = *reinterpret_cast<const ulonglong2*>(pa_base + kk * 128 + 4);
            ulonglong2 b01 = *reinterpret_cast<const ulonglong2*>(pb_base + kk * 256);
            ulonglong2 b23 = *reinterpret_cast<const ulonglong2*>(pb_base + kk * 256 + 4);
            ulonglong2 b45 = *reinterpret_cast<const ulonglong2*>(pb_base + kk * 256 + 8);
            ulonglong2 b67 = *reinterpret_cast<const ulonglong2*>(pb_base + kk * 256 + 12);
            unsigned long long ap[4] = { a01.x, a01.y, a23.x, a23.y };
            unsigned long long bp[8] = { b01.x, b01.y, b23.x, b23.y, b45.x, b45.y, b67.x, b67.y };
            #pragma unroll
            for (int j = 0; j < 8; ++j)
                #pragma unroll
                for (int i = 0; i < 4; ++i)
                    fma2(acc[j][i], ap[i], bp[j]);
        }
    }

    float av[8][8];
    #pragma unroll
    for (int j = 0; j < 8; ++j)
        #pragma unroll
        for (int i = 0; i < 4; ++i) upk2(acc[j][i], av[j][2 * i], av[j][2 * i + 1]);

    const float4 bo0 = *reinterpret_cast<const float4*>(&b_out[nt]);
    const float4 bo1 = *reinterpret_cast<const float4*>(&b_out[nt + 4]);

    #pragma unroll
    for (int p = 0; p < 8; ++p) {
        const size_t row = (size_t)((size_t)t * BATCH + bm0 + mt + p) * VOCAB;
        float4 w0 = make_float4(av[0][p] + bo0.x, av[1][p] + bo0.y,
                                av[2][p] + bo0.z, av[3][p] + bo0.w);
        float4 w1 = make_float4(av[4][p] + bo1.x, av[5][p] + bo1.y,
                                av[6][p] + bo1.z, av[7][p] + bo1.w);
        *reinterpret_cast<float4*>(&out[row + nt]) = w0;
        *reinterpret_cast<float4*>(&out[row + nt + 4]) = w1;
    }
}

// ---------------- tail: transpose hT, cT back to [b][h] -----------------------
__global__ void tail_kernel(float* __restrict__ out) {
    __shared__ float th[32][33], tc[32][33];
    const size_t baseH = (size_t)LSEQ * BATCH * VOCAB;
    const size_t nHB = (size_t)BATCH * HDIM;
    const float* hlast = g_HT + (size_t)LSEQ * HDIM * BATCH;  // [h][b]
    int bb = blockIdx.x * 32, hh = blockIdx.y * 32;
    int x = threadIdx.x, y = threadIdx.y;  // 32 x 8
    for (int i = y; i < 32; i += 8) {
        th[i][x] = hlast[(size_t)(hh + i) * BATCH + bb + x];
        tc[i][x] = g_CT[(size_t)(hh + i) * BATCH + bb + x];
    }
    __syncthreads();
    for (int i = y; i < 32; i += 8) {
        out[baseH + (size_t)(bb + i) * HDIM + hh + x] = th[x][i];
        out[baseH + nHB + (size_t)(bb + i) * HDIM + hh + x] = tc[x][i];
    }
}

// ---------------- launch -------------------------------------------------------
extern "C" void kernel_launch(void* const* d_in, const int* in_sizes, int n_in,
                              void* d_out, int out_size) {
    const int*   input = (const int*)  d_in[0];
    const float* h0    = (const float*)d_in[1];
    const float* c0    = (const float*)d_in[2];
    const float* emb   = (const float*)d_in[3];
    const float* W_ih  = (const float*)d_in[4];
    const float* W_hh  = (const float*)d_in[5];
    const float* b_ih  = (const float*)d_in[6];
    const float* b_hh  = (const float*)d_in[7];
    const float* W_out = (const float*)d_in[8];
    const float* b_out = (const float*)d_in[9];
    float* out = (float*)d_out;

    prep_kernel<<<2048, 256>>>(W_hh, W_out, b_ih, b_hh);
    xg_tab_kernel<<<(VOCAB * NG) / 256, 256>>>(emb, W_ih);
    transpose_in_kernel<<<dim3(BATCH / 32, HDIM / 32), dim3(32, 8)>>>(h0, c0);

    const int smem_bytes = (2 * 16 * 128 + 2 * 16 * 256) * sizeof(float);  // 49152
    dim3 stepGrid(BATCH / 128, NG / 128);  // 64 x 16
    for (int t = 0; t < LSEQ; ++t) {
        lstm_step_kernel<<<stepGrid, 256, smem_bytes>>>(t, input);
    }

    out_gemm_kernel<<<LSEQ * (BATCH / 128), 256, smem_bytes>>>(b_out, out);  // 3072 blocks

    tail_kernel<<<dim3(BATCH / 32, HDIM / 32), dim3(32, 8)>>>(out);
}

// round 4
// speedup vs baseline: 4.7929x; 4.7929x over previous
#include <cuda_runtime.h>
#include <cuda_bf16.h>
#include <cstdint>
#include <math.h>

// Problem constants
#define LSEQ 48
#define BATCH 8192
#define EDIM 50
#define HDIM 512
#define VOCAB 128
#define NG   (4 * HDIM)      // 2048 packed gate columns (n = h*4 + g)
#define KH   512             // K per segment
#define NCH  24              // 3 segments * 8 chunks of 64

// ---------------- scratch (static __device__ arrays; no allocation) ----------
__device__ __nv_bfloat16 g_Whi[(size_t)NG * KH];     // W_hh packed [n][k] hi
__device__ __nv_bfloat16 g_Wlo[(size_t)NG * KH];     // lo
__device__ __nv_bfloat16 g_Wohi[(size_t)VOCAB * KH]; // W_out [v][k] hi
__device__ __nv_bfloat16 g_Wolo[(size_t)VOCAB * KH]; // lo
__device__ float g_bsum[NG];                         // b_ih + b_hh, packed order
__device__ float g_Xg[(size_t)VOCAB * NG];           // emb @ W_ih^T, packed order
__device__ __nv_bfloat16 g_Ahi[(size_t)(LSEQ + 1) * BATCH * KH];  // h_t [t][b][k] hi
__device__ __nv_bfloat16 g_Alo[(size_t)(LSEQ + 1) * BATCH * KH];  // lo
__device__ float g_C[(size_t)BATCH * HDIM];          // cell state [b][h] fp32

// ---------------- helpers ----------------------------------------------------
__device__ __forceinline__ uint32_t smem_u32(const void* p) {
    return (uint32_t)__cvta_generic_to_shared(p);
}
#define CP16(dst, src) asm volatile("cp.async.cg.shared.global [%0], [%1], 16;" :: "r"(dst), "l"(src))
#define CP_COMMIT()    asm volatile("cp.async.commit_group;")
#define CP_WAIT0()     asm volatile("cp.async.wait_group 0;" ::: "memory")
#define CP_WAIT1()     asm volatile("cp.async.wait_group 1;" ::: "memory")

__device__ __forceinline__ void ldsm4(uint32_t& r0, uint32_t& r1, uint32_t& r2, uint32_t& r3,
                                      uint32_t addr) {
    asm volatile("ldmatrix.sync.aligned.m8n8.x4.shared.b16 {%0,%1,%2,%3}, [%4];"
                 : "=r"(r0), "=r"(r1), "=r"(r2), "=r"(r3) : "r"(addr));
}
__device__ __forceinline__ void mma16816(float* d, const uint32_t* a, uint32_t b0, uint32_t b1) {
    asm volatile("mma.sync.aligned.m16n8k16.row.col.f32.bf16.bf16.f32 "
                 "{%0,%1,%2,%3}, {%4,%5,%6,%7}, {%8,%9}, {%0,%1,%2,%3};"
                 : "+f"(d[0]), "+f"(d[1]), "+f"(d[2]), "+f"(d[3])
                 : "r"(a[0]), "r"(a[1]), "r"(a[2]), "r"(a[3]), "r"(b0), "r"(b1));
}
__device__ __forceinline__ float sigm(float x) { return 1.0f / (1.0f + __expf(-x)); }
__device__ __forceinline__ float tanh_fast(float x) { return 2.0f * sigm(2.0f * x) - 1.0f; }
__device__ __forceinline__ void split_bf16(float x, __nv_bfloat16& hi, __nv_bfloat16& lo) {
    hi = __float2bfloat16_rn(x);
    lo = __float2bfloat16_rn(x - __bfloat162float(hi));
}

// ---------------- cp.async tile loader (A and B chunk -> swizzled SMEM) -------
// chunk 0-7: Ahi*Bhi, 8-15: Ahi*Blo, 16-23: Alo*Bhi.  BK=64 bf16 = 128B rows.
__device__ __forceinline__ void issue_tile_loads(
    int chunk, uint32_t Asm, uint32_t Bsm,
    const __nv_bfloat16* __restrict__ Ahi, const __nv_bfloat16* __restrict__ Alo,
    const __nv_bfloat16* __restrict__ Bhi, const __nv_bfloat16* __restrict__ Blo,
    int bm0, int n0, int tid)
{
    const int seg = chunk >> 3;
    const int k0  = (chunk & 7) * 64;
    const int s   = chunk & 1;
    const __nv_bfloat16* Ab = (seg < 2) ? Ahi : Alo;
    const __nv_bfloat16* Bb = (seg == 1) ? Blo : Bhi;
    const int r  = tid >> 1;             // 0..127
    const int j0 = (tid & 1) * 4;        // 0 or 4 (16B chunks)
    const __nv_bfloat16* ga = Ab + ((size_t)(bm0 + r) << 9) + k0 + j0 * 8;
    const __nv_bfloat16* gb = Bb + ((size_t)(n0 + r) << 9) + k0 + j0 * 8;
    const uint32_t abase = Asm + s * 16384, bbase = Bsm + s * 16384;
    #pragma unroll
    for (int j = 0; j < 4; ++j) {
        uint32_t off = r * 128 + (j0 + j) * 16;
        uint32_t sw  = off ^ ((off >> 3) & 0x70);
        CP16(abase + sw, ga + j * 8);
        CP16(bbase + sw, gb + j * 8);
    }
    CP_COMMIT();
}

// ---------------- one BK=64 chunk of HMMA compute ------------------------------
__device__ __forceinline__ void compute_chunk(uint32_t sAb, uint32_t sBb,
                                              int wm, int wn, int lane,
                                              float acc[4][4][4]) {
    #pragma unroll
    for (int kk = 0; kk < 4; ++kk) {
        uint32_t a[4][4];
        #pragma unroll
        for (int mi = 0; mi < 4; ++mi) {
            int r  = wm + 16 * mi + (lane & 15);
            int kb = kk * 32 + ((lane >> 4) << 4);
            uint32_t off = (uint32_t)(r * 128 + kb);
            off ^= (off >> 3) & 0x70;
            ldsm4(a[mi][0], a[mi][1], a[mi][2], a[mi][3], sAb + off);
        }
        uint32_t b[2][4];
        #pragma unroll
        for (int nj2 = 0; nj2 < 2; ++nj2) {
            int r  = wn + nj2 * 16 + ((lane >> 4) << 3) + (lane & 7);
            int kb = kk * 32 + ((lane & 8) ? 16 : 0);
            uint32_t off = (uint32_t)(r * 128 + kb);
            off ^= (off >> 3) & 0x70;
            ldsm4(b[nj2][0], b[nj2][1], b[nj2][2], b[nj2][3], sBb + off);
        }
        #pragma unroll
        for (int mi = 0; mi < 4; ++mi)
            #pragma unroll
            for (int nj = 0; nj < 4; ++nj)
                mma16816(acc[mi][nj], a[mi],
                         b[nj >> 1][(nj & 1) * 2], b[nj >> 1][(nj & 1) * 2 + 1]);
    }
}

// ---------------- prep kernels -------------------------------------------------
__global__ void prep_w_kernel(const float* __restrict__ W_hh,
                              const float* __restrict__ W_out,
                              const float* __restrict__ b_ih,
                              const float* __restrict__ b_hh) {
    const size_t nW = (size_t)NG * KH;
    for (size_t i = (size_t)blockIdx.x * blockDim.x + threadIdx.x; i < nW;
         i += (size_t)gridDim.x * blockDim.x) {
        int n = (int)(i >> 9), k = (int)(i & 511);
        int h = n >> 2, g = n & 3;
        split_bf16(W_hh[(size_t)(g * HDIM + h) * HDIM + k], g_Whi[i], g_Wlo[i]);
    }
    const size_t nWo = (size_t)VOCAB * KH;
    for (size_t i = (size_t)blockIdx.x * blockDim.x + threadIdx.x; i < nWo;
         i += (size_t)gridDim.x * blockDim.x) {
        split_bf16(W_out[i], g_Wohi[i], g_Wolo[i]);
    }
    int j = blockIdx.x * blockDim.x + threadIdx.x;
    if (j < NG) {
        int h = j >> 2, g = j & 3;
        g_bsum[j] = b_ih[g * HDIM + h] + b_hh[g * HDIM + h];
    }
}

__global__ void prep_h_kernel(const float* __restrict__ h0, const float* __restrict__ c0) {
    const size_t n = (size_t)BATCH * HDIM;
    for (size_t i = (size_t)blockIdx.x * blockDim.x + threadIdx.x; i < n;
         i += (size_t)gridDim.x * blockDim.x) {
        split_bf16(h0[i], g_Ahi[i], g_Alo[i]);
        g_C[i] = c0[i];
    }
}

__global__ void xg_tab_kernel(const float* __restrict__ emb, const float* __restrict__ W_ih) {
    int i = blockIdx.x * blockDim.x + threadIdx.x;
    if (i >= VOCAB * NG) return;
    int v = i >> 11, n = i & (NG - 1);
    int h = n >> 2, g = n & 3;
    const float* er = emb + (size_t)v * EDIM;
    const float* wr = W_ih + (size_t)(g * HDIM + h) * EDIM;
    float s = 0.0f;
    #pragma unroll
    for (int e = 0; e < EDIM; ++e) s += er[e] * wr[e];
    g_Xg[i] = s;
}

// ---------------- fused gate GEMM + LSTM cell (one step) ----------------------
#define SC_STRIDE 132
__global__ __launch_bounds__(256)
void lstm_step_kernel(int t, const int* __restrict__ input) {
    extern __shared__ char dsm[];
    const uint32_t tile = (smem_u32(dsm) + 1023) & ~1023u;
    const uint32_t Asm = tile;            // 2 stages x 16384 B
    const uint32_t Bsm = tile + 32768;    // 2 stages x 16384 B
    float* sC = reinterpret_cast<float*>(dsm + (tile - smem_u32(dsm)));  // reuse tiles

    const int tid  = threadIdx.x;
    const int lane = tid & 31;
    const int w    = tid >> 5;
    const int wm   = (w & 1) * 64;
    const int wn   = (w >> 1) * 32;
    const int bm0  = blockIdx.x * 128;
    const int n0   = blockIdx.y * 128;

    const __nv_bfloat16* Ahi = g_Ahi + (size_t)t * BATCH * KH;
    const __nv_bfloat16* Alo = g_Alo + (size_t)t * BATCH * KH;

    float acc[4][4][4];
    #pragma unroll
    for (int mi = 0; mi < 4; ++mi)
        #pragma unroll
        for (int nj = 0; nj < 4; ++nj)
            #pragma unroll
            for (int q = 0; q < 4; ++q) acc[mi][nj][q] = 0.0f;

    issue_tile_loads(0, Asm, Bsm, Ahi, Alo, g_Whi, g_Wlo, bm0, n0, tid);
    issue_tile_loads(1, Asm, Bsm, Ahi, Alo, g_Whi, g_Wlo, bm0, n0, tid);

    for (int i = 0; i < NCH; ++i) {
        const int s = i & 1;
        if (i + 1 < NCH) CP_WAIT1(); else CP_WAIT0();
        __syncthreads();
        compute_chunk(Asm + s * 16384, Bsm + s * 16384, wm, wn, lane, acc);
        __syncthreads();
        if (i + 2 < NCH)
            issue_tile_loads(i + 2, Asm, Bsm, Ahi, Alo, g_Whi, g_Wlo, bm0, n0, tid);
    }

    // ---- epilogue: regroup gates via smem, apply LSTM cell ----
    #pragma unroll
    for (int mi = 0; mi < 4; ++mi)
        #pragma unroll
        for (int nj = 0; nj < 4; ++nj) {
            int r0 = wm + 16 * mi + (lane >> 2);
            int c  = wn + 8 * nj + 2 * (lane & 3);
            *reinterpret_cast<float2*>(&sC[r0 * SC_STRIDE + c]) =
                make_float2(acc[mi][nj][0], acc[mi][nj][1]);
            *reinterpret_cast<float2*>(&sC[(r0 + 8) * SC_STRIDE + c]) =
                make_float2(acc[mi][nj][2], acc[mi][nj][3]);
        }
    __syncthreads();

    const int m = tid >> 1;
    const int half = tid & 1;
    const int b = bm0 + m;
    const int v = input[(size_t)t * BATCH + b];
    const int hbase = (n0 >> 2) + half * 16;       // 16 consecutive h per thread
    __nv_bfloat16* Hhi = g_Ahi + (size_t)(t + 1) * BATCH * KH + (size_t)b * KH + hbase;
    __nv_bfloat16* Hlo = g_Alo + (size_t)(t + 1) * BATCH * KH + (size_t)b * KH + hbase;
    float* Crow = g_C + (size_t)b * HDIM + hbase;

    __align__(16) __nv_bfloat16 hh[16], hl[16];
    __align__(16) float cn16[16];
    #pragma unroll
    for (int i = 0; i < 16; ++i) {
        const int lh = half * 16 + i;              // local h in tile (0..31)
        float4 gq = *reinterpret_cast<const float4*>(&sC[m * SC_STRIDE + lh * 4]);
        const int n = n0 + lh * 4;
        float4 bs = *reinterpret_cast<const float4*>(&g_bsum[n]);
        float4 xg = *reinterpret_cast<const float4*>(&g_Xg[(size_t)v * NG + n]);
        float gi = gq.x + bs.x + xg.x;
        float gf = gq.y + bs.y + xg.y;
        float gg = gq.z + bs.z + xg.z;
        float go = gq.w + bs.w + xg.w;
        float cn = sigm(gf) * Crow[i] + sigm(gi) * tanh_fast(gg);
        cn16[i] = cn;
        split_bf16(sigm(go) * tanh_fast(cn), hh[i], hl[i]);
    }
    #pragma unroll
    for (int q = 0; q < 4; ++q)
        *reinterpret_cast<float4*>(&Crow[q * 4]) = *reinterpret_cast<float4*>(&cn16[q * 4]);
    *reinterpret_cast<uint4*>(&Hhi[0]) = *reinterpret_cast<uint4*>(&hh[0]);
    *reinterpret_cast<uint4*>(&Hhi[8]) = *reinterpret_cast<uint4*>(&hh[8]);
    *reinterpret_cast<uint4*>(&Hlo[0]) = *reinterpret_cast<uint4*>(&hl[0]);
    *reinterpret_cast<uint4*>(&Hlo[8]) = *reinterpret_cast<uint4*>(&hl[8]);
}

// ---------------- batched output projection ------------------------------------
__global__ __launch_bounds__(256)
void out_gemm_kernel(const float* __restrict__ b_out, float* __restrict__ out) {
    extern __shared__ char dsm[];
    const uint32_t tile = (smem_u32(dsm) + 1023) & ~1023u;
    const uint32_t Asm = tile;
    const uint32_t Bsm = tile + 32768;

    const int tid  = threadIdx.x;
    const int lane = tid & 31;
    const int w    = tid >> 5;
    const int wm   = (w & 1) * 64;
    const int wn   = (w >> 1) * 32;
    const int t    = blockIdx.x >> 6;
    const int bm0  = (blockIdx.x & 63) * 128;

    const __nv_bfloat16* Ahi = g_Ahi + (size_t)(t + 1) * BATCH * KH;
    const __nv_bfloat16* Alo = g_Alo + (size_t)(t + 1) * BATCH * KH;

    float acc[4][4][4];
    #pragma unroll
    for (int mi = 0; mi < 4; ++mi)
        #pragma unroll
        for (int nj = 0; nj < 4; ++nj)
            #pragma unroll
            for (int q = 0; q < 4; ++q) acc[mi][nj][q] = 0.0f;

    issue_tile_loads(0, Asm, Bsm, Ahi, Alo, g_Wohi, g_Wolo, bm0, 0, tid);
    issue_tile_loads(1, Asm, Bsm, Ahi, Alo, g_Wohi, g_Wolo, bm0, 0, tid);

    for (int i = 0; i < NCH; ++i) {
        const int s = i & 1;
        if (i + 1 < NCH) CP_WAIT1(); else CP_WAIT0();
        __syncthreads();
        compute_chunk(Asm + s * 16384, Bsm + s * 16384, wm, wn, lane, acc);
        __syncthreads();
        if (i + 2 < NCH)
            issue_tile_loads(i + 2, Asm, Bsm, Ahi, Alo, g_Wohi, g_Wolo, bm0, 0, tid);
    }

    // epilogue: direct register writes, + bias
    const size_t rowbase = (size_t)t * BATCH + bm0;
    #pragma unroll
    for (int mi = 0; mi < 4; ++mi)
        #pragma unroll
        for (int nj = 0; nj < 4; ++nj) {
            int r0 = wm + 16 * mi + (lane >> 2);
            int c  = wn + 8 * nj + 2 * (lane & 3);
            float2 bo = *reinterpret_cast<const float2*>(&b_out[c]);
            *reinterpret_cast<float2*>(&out[(rowbase + r0) * VOCAB + c]) =
                make_float2(acc[mi][nj][0] + bo.x, acc[mi][nj][1] + bo.y);
            *reinterpret_cast<float2*>(&out[(rowbase + r0 + 8) * VOCAB + c]) =
                make_float2(acc[mi][nj][2] + bo.x, acc[mi][nj][3] + bo.y);
        }
}

// ---------------- tail: final h (hi+lo) and c ---------------------------------
__global__ void tail_kernel(float* __restrict__ out) {
    const size_t baseH = (size_t)LSEQ * BATCH * VOCAB;
    const size_t n = (size_t)BATCH * HDIM;
    const __nv_bfloat16* Hhi = g_Ahi + (size_t)LSEQ * BATCH * KH;
    const __nv_bfloat16* Hlo = g_Alo + (size_t)LSEQ * BATCH * KH;
    for (size_t i = (size_t)blockIdx.x * blockDim.x + threadIdx.x; i < n;
         i += (size_t)gridDim.x * blockDim.x) {
        out[baseH + i] = __bfloat162float(Hhi[i]) + __bfloat162float(Hlo[i]);
        out[baseH + n + i] = g_C[i];
    }
}

// ---------------- launch -------------------------------------------------------
extern "C" void kernel_launch(void* const* d_in, const int* in_sizes, int n_in,
                              void* d_out, int out_size) {
    const int*   input = (const int*)  d_in[0];
    const float* h0    = (const float*)d_in[1];
    const float* c0    = (const float*)d_in[2];
    const float* emb   = (const float*)d_in[3];
    const float* W_ih  = (const float*)d_in[4];
    const float* W_hh  = (const float*)d_in[5];
    const float* b_ih  = (const float*)d_in[6];
    const float* b_hh  = (const float*)d_in[7];
    const float* W_out = (const float*)d_in[8];
    const float* b_out = (const float*)d_in[9];
    float* out = (float*)d_out;

    // 1KB align pad + max(tiles 64KB, sC 128*132*4 = 67584B)
    const int smem_bytes = 1024 + 128 * SC_STRIDE * 4;
    cudaFuncSetAttribute(lstm_step_kernel, cudaFuncAttributeMaxDynamicSharedMemorySize, smem_bytes);
    cudaFuncSetAttribute(out_gemm_kernel, cudaFuncAttributeMaxDynamicSharedMemorySize, smem_bytes);

    prep_w_kernel<<<1024, 256>>>(W_hh, W_out, b_ih, b_hh);
    prep_h_kernel<<<1024, 256>>>(h0, c0);
    xg_tab_kernel<<<(VOCAB * NG) / 256, 256>>>(emb, W_ih);

    dim3 stepGrid(BATCH / 128, NG / 128);  // 64 x 16 = 1024 CTAs
    for (int t = 0; t < LSEQ; ++t) {
        lstm_step_kernel<<<stepGrid, 256, smem_bytes>>>(t, input);
    }

    out_gemm_kernel<<<LSEQ * (BATCH / 128), 256, smem_bytes>>>(b_out, out);  // 3072 CTAs

    tail_kernel<<<4096, 256>>>(out);
}